// round 7
// baseline (speedup 1.0000x reference)
#include <cuda_runtime.h>
#include <cuda_bf16.h>
#include <cstdint>

#define NHEAD 16
#define DIM   64
#define BS    64
#define NSEL  16
// SCALE * log2(e): softmax runs in base-2 domain
#define SCALE2 0.18033688011112042f
#define STRIDE 68            // floats per smem row; 68%32==4 -> (4r+c) bank pattern
#define FULL 0xffffffffu

__device__ __forceinline__ unsigned f2tf(float f) {
    unsigned r; asm("cvt.rna.tf32.f32 %0, %1;" : "=r"(r) : "f"(f)); return r;
}

__device__ __forceinline__ void mma_tf32(float c[4], const unsigned a[4],
                                         unsigned b0, unsigned b1) {
    asm volatile(
        "mma.sync.aligned.m16n8k8.row.col.f32.tf32.tf32.f32 "
        "{%0,%1,%2,%3}, {%4,%5,%6,%7}, {%8,%9}, {%0,%1,%2,%3};\n"
        : "+f"(c[0]), "+f"(c[1]), "+f"(c[2]), "+f"(c[3])
        : "r"(a[0]), "r"(a[1]), "r"(a[2]), "r"(a[3]), "r"(b0), "r"(b1));
}

__device__ __forceinline__ void cpa16(uint32_t saddr, const void* gaddr) {
    asm volatile("cp.async.cg.shared.global [%0], [%1], 16;\n"
                 :: "r"(saddr), "l"(gaddr));
}
__device__ __forceinline__ void cpa_commit() {
    asm volatile("cp.async.commit_group;\n");
}
template <int N>
__device__ __forceinline__ void cpa_wait() {
    asm volatile("cp.async.wait_group %0;\n" :: "n"(N));
}

// stage one 32x64 half-block into a padded smem tile and commit as one group
__device__ __forceinline__ void stage_half(uint32_t sbase, const float* src, int ln) {
    const char* g = reinterpret_cast<const char*>(src);
    #pragma unroll
    for (int i = 0; i < 16; ++i) {
        int e = ln + 32 * i;
        uint32_t off = (uint32_t)((e >> 4) * STRIDE + (e & 15) * 4) * 4u;
        cpa16(sbase + off, g + e * 16);
    }
    cpa_commit();
}

__global__ __launch_bounds__(32, 13)
void nsa_tc_kernel(const float* __restrict__ Q, const float* __restrict__ K,
                   const float* __restrict__ V, const int* __restrict__ BIdx,
                   float* __restrict__ Out)
{
    // Reverse mapping: expensive tokens (large t = most valid blocks) start
    // first; the partial last wave gets the cheapest tokens.
    const int t  = (int)gridDim.x - 1 - (int)blockIdx.x;
    const int ln = threadIdx.x;
    const int r4 = ln >> 2;          // 0..7  (fragment "group")
    const int c4 = ln & 3;           // 0..3  (thread in group)

    __shared__ __align__(16) float Ks[32][STRIDE];
    __shared__ __align__(16) float Vs[32][STRIDE];
    __shared__ int kb[34];           // valid half-block bases (+1 dummy)

    // ---- stage Q (16x64) through Ks, build resident tf32 A-fragments ----
    {
        const float4* Qg = reinterpret_cast<const float4*>(Q + (size_t)t * NHEAD * DIM);
        #pragma unroll
        for (int i = 0; i < 8; ++i) {
            int e = ln + 32 * i;
            *reinterpret_cast<float4*>(&Ks[e >> 4][(e & 15) * 4]) = Qg[e];
        }
    }
    __syncwarp();
    unsigned qa[8][4];
    #pragma unroll
    for (int kc = 0; kc < 8; ++kc) {
        qa[kc][0] = f2tf(Ks[r4    ][kc * 8 + c4    ] * SCALE2);
        qa[kc][1] = f2tf(Ks[r4 + 8][kc * 8 + c4    ] * SCALE2);
        qa[kc][2] = f2tf(Ks[r4    ][kc * 8 + c4 + 4] * SCALE2);
        qa[kc][3] = f2tf(Ks[r4 + 8][kc * 8 + c4 + 4] * SCALE2);
    }

    // ---- build list of causally-valid 32-key halves (uniform control) ----
    int myblk = (ln < NSEL) ? BIdx[t * NSEL + ln] : 0;
    int n = 0;
    #pragma unroll
    for (int s = 0; s < NSEL; ++s) {
        int base = __shfl_sync(FULL, myblk, s) * BS;
        if (base <= t) {
            if (ln == 0) kb[n] = base;
            n++;
            if (base + 32 <= t) {
                if (ln == 0) kb[n] = base + 32;
                n++;
            }
        }
    }
    if (ln == 0) kb[n] = kb[n - 1];   // dummy prefetch target for last iteration
    __syncwarp();

    float oc[8][4];
    #pragma unroll
    for (int i = 0; i < 8; ++i) { oc[i][0] = oc[i][1] = oc[i][2] = oc[i][3] = 0.f; }
    float m0 = -1e30f, m1 = -1e30f, l0 = 0.f, l1 = 0.f;

    const uint32_t ks_base = (uint32_t)__cvta_generic_to_shared(&Ks[0][0]);
    const uint32_t vs_base = (uint32_t)__cvta_generic_to_shared(&Vs[0][0]);

    // ---- prologue: K[0] then V[0] in flight ----
    stage_half(ks_base, K + (size_t)kb[0] * DIM, ln);
    stage_half(vs_base, V + (size_t)kb[0] * DIM, ln);

    // Commit order is strictly K0,V0,K1,V1,...  so both wait points are a
    // constant wait_group<1> (the most recent group may remain in flight).
    for (int j = 0; j < n; ++j) {
        const int kbase = kb[j];
        const int knext = kb[j + 1];

        cpa_wait<1>();                          // K[j] resident (V[j] in flight)
        __syncwarp();

        // ---- QK: 4 key-tiles x 8 k-chunks of tf32 mma ----
        float sc[4][4];
        #pragma unroll
        for (int nt = 0; nt < 4; ++nt) { sc[nt][0] = sc[nt][1] = sc[nt][2] = sc[nt][3] = 0.f; }
        #pragma unroll
        for (int nt = 0; nt < 4; ++nt) {
            #pragma unroll
            for (int kc = 0; kc < 8; ++kc) {
                unsigned b0 = f2tf(Ks[nt * 8 + r4][kc * 8 + c4    ]);
                unsigned b1 = f2tf(Ks[nt * 8 + r4][kc * 8 + c4 + 4]);
                mma_tf32(sc[nt], qa[kc], b0, b1);
            }
        }

        // Ks consumed -> prefetch K[j+1] into the same buffer (writes land
        // hundreds of cycles after the LDS reads above have issued).
        stage_half(ks_base, K + (size_t)knext * DIM, ln);

        // ---- causal mask + online softmax (base-2 domain, quad shuffles) ----
        float mx0 = -1e30f, mx1 = -1e30f;
        #pragma unroll
        for (int nt = 0; nt < 4; ++nt) {
            int p0 = kbase + nt * 8 + 2 * c4;
            if (p0     > t) { sc[nt][0] = -1e30f; sc[nt][2] = -1e30f; }
            if (p0 + 1 > t) { sc[nt][1] = -1e30f; sc[nt][3] = -1e30f; }
            mx0 = fmaxf(mx0, fmaxf(sc[nt][0], sc[nt][1]));
            mx1 = fmaxf(mx1, fmaxf(sc[nt][2], sc[nt][3]));
        }
        #pragma unroll
        for (int o = 1; o < 4; o <<= 1) {
            mx0 = fmaxf(mx0, __shfl_xor_sync(FULL, mx0, o));
            mx1 = fmaxf(mx1, __shfl_xor_sync(FULL, mx1, o));
        }
        float mn0 = fmaxf(m0, mx0), mn1 = fmaxf(m1, mx1);
        float al0 = exp2f(m0 - mn0), al1 = exp2f(m1 - mn1);
        m0 = mn0; m1 = mn1;
        float sum0 = 0.f, sum1 = 0.f;
        #pragma unroll
        for (int nt = 0; nt < 4; ++nt) {
            sc[nt][0] = exp2f(sc[nt][0] - mn0);
            sc[nt][1] = exp2f(sc[nt][1] - mn0);
            sc[nt][2] = exp2f(sc[nt][2] - mn1);
            sc[nt][3] = exp2f(sc[nt][3] - mn1);
            sum0 += sc[nt][0] + sc[nt][1];
            sum1 += sc[nt][2] + sc[nt][3];
        }
        #pragma unroll
        for (int o = 1; o < 4; o <<= 1) {
            sum0 += __shfl_xor_sync(FULL, sum0, o);
            sum1 += __shfl_xor_sync(FULL, sum1, o);
        }
        l0 = l0 * al0 + sum0;
        l1 = l1 * al1 + sum1;
        #pragma unroll
        for (int nt = 0; nt < 8; ++nt) {
            oc[nt][0] *= al0; oc[nt][1] *= al0;
            oc[nt][2] *= al1; oc[nt][3] *= al1;
        }

        // ---- P: C-fragment -> A-fragment via quad shuffles (V-independent,
        //      kept ahead of the V wait to sit in its latency shadow) ----
        unsigned pa[4][4];
        {
            int srcA = (ln & ~3) | (c4 >> 1);
            int srcB = srcA + 2;
            bool par = (c4 & 1);
            #pragma unroll
            for (int kk = 0; kk < 4; ++kk) {
                float v0a = __shfl_sync(FULL, sc[kk][0], srcA);
                float v1a = __shfl_sync(FULL, sc[kk][1], srcA);
                float v2a = __shfl_sync(FULL, sc[kk][2], srcA);
                float v3a = __shfl_sync(FULL, sc[kk][3], srcA);
                float v0b = __shfl_sync(FULL, sc[kk][0], srcB);
                float v1b = __shfl_sync(FULL, sc[kk][1], srcB);
                float v2b = __shfl_sync(FULL, sc[kk][2], srcB);
                float v3b = __shfl_sync(FULL, sc[kk][3], srcB);
                pa[kk][0] = f2tf(par ? v1a : v0a);
                pa[kk][1] = f2tf(par ? v3a : v2a);
                pa[kk][2] = f2tf(par ? v1b : v0b);
                pa[kk][3] = f2tf(par ? v3b : v2b);
            }
        }

        cpa_wait<1>();                          // V[j] resident (K[j+1] in flight)
        __syncwarp();

        // ---- PV: 8 dim-tiles x 4 key-chunks ----
        #pragma unroll
        for (int nt = 0; nt < 8; ++nt) {
            #pragma unroll
            for (int kk = 0; kk < 4; ++kk) {
                unsigned b0 = f2tf(Vs[kk * 8 + c4    ][nt * 8 + r4]);
                unsigned b1 = f2tf(Vs[kk * 8 + c4 + 4][nt * 8 + r4]);
                mma_tf32(oc[nt], pa[kk], b0, b1);
            }
        }

        // Vs consumed -> prefetch V[j+1]
        stage_half(vs_base, V + (size_t)knext * DIM, ln);
    }

    cpa_wait<0>();                               // drain dummy prefetches
    __syncwarp();

    // ---- normalize + write: rows r4 / r4+8, float2 per tile ----
    float inv0 = 1.0f / l0, inv1 = 1.0f / l1;
    float* Og = Out + (size_t)t * NHEAD * DIM;
    #pragma unroll
    for (int nt = 0; nt < 8; ++nt) {
        int col = nt * 8 + 2 * c4;
        *reinterpret_cast<float2*>(&Og[r4 * DIM + col]) =
            make_float2(oc[nt][0] * inv0, oc[nt][1] * inv0);
        *reinterpret_cast<float2*>(&Og[(r4 + 8) * DIM + col]) =
            make_float2(oc[nt][2] * inv1, oc[nt][3] * inv1);
    }
}

extern "C" void kernel_launch(void* const* d_in, const int* in_sizes, int n_in,
                              void* d_out, int out_size)
{
    const float* Q    = (const float*)d_in[0];
    const float* K    = (const float*)d_in[1];
    const float* V    = (const float*)d_in[2];
    const int*   BIdx = (const int*)d_in[3];
    float*       Out  = (float*)d_out;

    const int T = in_sizes[0] / (NHEAD * DIM);   // 2048
    nsa_tc_kernel<<<T, 32>>>(Q, K, V, BIdx, Out);
}